// round 15
// baseline (speedup 1.0000x reference)
#include <cuda_runtime.h>
#include <cstdint>

#define BATCH 4
#define NPTS  8192
#define GDIM  64                  // grid cells per axis
#define NCELL (GDIM * GDIM)       // 4096
#define CAP   20                  // max pts/cell (lambda=2; P(overflow)~1e-14)
#define HCELL (1.0f / GDIM)
#define NTAB  (2 * BATCH)         // set s (0=pred,1=gt) x batch
#define NQ    (2 * BATCH * NPTS)  // 65536 points == queries
#define NTHR  256
#define TPQ   8                   // threads per query
#define NSB   (TPQ * NQ / NTHR)   // 2048 search blocks
#define FINF  3.4e38f

// Persistent scratch (zero at load; search's last block re-zeros counts).
// Slots beyond a cell's count hold stale-but-finite data; all reads are
// predicated on the count, so stale content is never observable.
__device__ int      g_ccnt[NTAB * NCELL];
__device__ float2   g_cell[NTAB * NCELL * CAP];    // 5.2 MB (L2-resident)
__device__ float    g_part[NSB];
__device__ unsigned g_done;

// ============================================================================
// K1: bin all points (atomicAdd slot; drop on overflow - P~0)
// ============================================================================
__global__ __launch_bounds__(NTHR) void k_fill(const float2* __restrict__ pred,
                                               const float2* __restrict__ gt) {
    int gid = blockIdx.x * NTHR + threadIdx.x;         // 0..65535
    int s = gid >> 15, b = (gid >> 13) & 3, i = gid & (NPTS - 1);
    const float2* src = s ? gt : pred;
    float2 p = src[b * NPTS + i];
    int cx = min(GDIM - 1, max(0, (int)(p.x * (float)GDIM)));
    int cy = min(GDIM - 1, max(0, (int)(p.y * (float)GDIM)));
    int cell = (s * BATCH + b) * NCELL + cy * GDIM + cx;
    int pos = atomicAdd(&g_ccnt[cell], 1);
    if (pos < CAP) g_cell[cell * CAP + pos] = p;
}

__device__ __forceinline__ void scan_cell(int cbase, int c, float qx, float qy,
                                          float& best) {
    int n = min(g_ccnt[cbase + c], CAP);
    const float2* p = &g_cell[(cbase + c) * CAP];
    for (int j = 0; j < n; j++) {
        float2 t = p[j];
        float dx = qx - t.x, dy = qy - t.y;
        best = fminf(best, fmaf(dx, dx, dy * dy));
    }
}

// ============================================================================
// K2: exact NN, EIGHT threads per query (adjacent lanes; sub = tgid&7).
// Branchless hot path: sub k owns cell cid9[k] (cells 0..7); cell 8's slots
// 0..7 are spread one-per-sub. Counts + slots 0..7 loaded UNCONDITIONALLY
// (addresses independent of counts -> all LDGs front-batch); validity applied
// by predication -> ZERO data-dependent loops in the common case, so no
// divergence inflation. Tails (n>8; P~2e-4/cell) behind one __any_sync.
// Combine via shfl_xor 1/2/4. Stragglers (best > H^2 after 3x3; P~0.2%):
// sub 0 runs expanding Chebyshev rings (ring-k cells >= (k-1)*H away -> exact
// termination). Deterministic: mins/termination depend only on candidate
// sets; final sums are fixed-order trees.
// ============================================================================
__global__ __launch_bounds__(NTHR) void k_search(const float2* __restrict__ pred,
                                                 const float2* __restrict__ gt,
                                                 float* __restrict__ out) {
    const int t = threadIdx.x, bid = blockIdx.x;
    const int tgid = bid * NTHR + t;                   // 0..524287
    const int gid = tgid >> 3, sub = tgid & 7;         // query id, sub id
    const int s = gid >> 15, b = (gid >> 13) & 3, i = gid & (NPTS - 1);

    const float2* qsrc = s ? gt : pred;
    const float2 q = qsrc[b * NPTS + i];
    const int cbase = ((s ^ 1) * BATCH + b) * NCELL;   // other set's table

    const int cx = min(GDIM - 1, max(0, (int)(q.x * (float)GDIM)));
    const int cy = min(GDIM - 1, max(0, (int)(q.y * (float)GDIM)));

    // 3x3 cell ids (clamped; duplicates OK - min is idempotent)
    const int xm = max(cx - 1, 0), xp = min(cx + 1, GDIM - 1);
    const int ym = max(cy - 1, 0), yp = min(cy + 1, GDIM - 1);
    int cid9[9];
    cid9[0] = ym * GDIM + xm; cid9[1] = ym * GDIM + cx; cid9[2] = ym * GDIM + xp;
    cid9[3] = cy * GDIM + xm; cid9[4] = cy * GDIM + cx; cid9[5] = cy * GDIM + xp;
    cid9[6] = yp * GDIM + xm; cid9[7] = yp * GDIM + cx; cid9[8] = yp * GDIM + xp;

    const int cA = cid9[sub];                          // my main cell
    const int c8 = cid9[8];                            // shared 9th cell

    // Front-batched independent loads (no dependence on counts)
    const int   nA = g_ccnt[cbase + cA];
    const int   n8 = g_ccnt[cbase + c8];
    const float4* p4 = (const float4*)&g_cell[(cbase + cA) * CAP];
    const float4  A = p4[0], B = p4[1], C = p4[2], D = p4[3];   // slots 0..7
    const float2  e8 = g_cell[(cbase + c8) * CAP + sub];        // slot 'sub'

    float best = FINF;
    {
        float dx, dy, d;
        dx = q.x - A.x; dy = q.y - A.y; d = fmaf(dx, dx, dy * dy);
        best = fminf(best, (0 < nA) ? d : FINF);
        dx = q.x - A.z; dy = q.y - A.w; d = fmaf(dx, dx, dy * dy);
        best = fminf(best, (1 < nA) ? d : FINF);
        dx = q.x - B.x; dy = q.y - B.y; d = fmaf(dx, dx, dy * dy);
        best = fminf(best, (2 < nA) ? d : FINF);
        dx = q.x - B.z; dy = q.y - B.w; d = fmaf(dx, dx, dy * dy);
        best = fminf(best, (3 < nA) ? d : FINF);
        dx = q.x - C.x; dy = q.y - C.y; d = fmaf(dx, dx, dy * dy);
        best = fminf(best, (4 < nA) ? d : FINF);
        dx = q.x - C.z; dy = q.y - C.w; d = fmaf(dx, dx, dy * dy);
        best = fminf(best, (5 < nA) ? d : FINF);
        dx = q.x - D.x; dy = q.y - D.y; d = fmaf(dx, dx, dy * dy);
        best = fminf(best, (6 < nA) ? d : FINF);
        dx = q.x - D.z; dy = q.y - D.w; d = fmaf(dx, dx, dy * dy);
        best = fminf(best, (7 < nA) ? d : FINF);
        // cell 8, slot 'sub'
        dx = q.x - e8.x; dy = q.y - e8.y; d = fmaf(dx, dx, dy * dy);
        best = fminf(best, (sub < n8) ? d : FINF);
    }

    // Ultra-rare tails (n>8): one warp-uniform branch
    bool tailA = (nA > 8);
    bool tail8 = (sub == 0) && (n8 > 8);
    if (__any_sync(0xFFFFFFFFu, tailA || tail8)) {
        if (tailA) {
            int n = min(nA, CAP);
            const float2* p = &g_cell[(cbase + cA) * CAP];
            for (int u = 8; u < n; u++) {
                float dx = q.x - p[u].x, dy = q.y - p[u].y;
                best = fminf(best, fmaf(dx, dx, dy * dy));
            }
        }
        if (tail8) {
            int n = min(n8, CAP);
            const float2* p = &g_cell[(cbase + c8) * CAP];
            for (int u = 8; u < n; u++) {
                float dx = q.x - p[u].x, dy = q.y - p[u].y;
                best = fminf(best, fmaf(dx, dx, dy * dy));
            }
        }
    }

    // Combine the 8 sub-threads (lanes 8k..8k+7)
    best = fminf(best, __shfl_xor_sync(0xFFFFFFFFu, best, 1));
    best = fminf(best, __shfl_xor_sync(0xFFFFFFFFu, best, 2));
    best = fminf(best, __shfl_xor_sync(0xFFFFFFFFu, best, 4));

    // Straggler rings on sub 0 only (P ~ 0.2% of queries)
    if (__any_sync(0xFFFFFFFFu, sub == 0 && best > HCELL * HCELL)) {
        if (sub == 0 && best > HCELL * HCELL) {
            #pragma unroll 1
            for (int k = 2; k < GDIM; k++) {
                float rd = (float)(k - 1) * HCELL;
                if (best <= rd * rd) break;
                int y0 = max(cy - k, 0), y1 = min(cy + k, GDIM - 1);
                int x0 = max(cx - k, 0), x1 = min(cx + k, GDIM - 1);
                for (int yy = y0; yy <= y1; yy++) {
                    if (yy == cy - k || yy == cy + k) {
                        for (int xx = x0; xx <= x1; xx++)
                            scan_cell(cbase, yy * GDIM + xx, q.x, q.y, best);
                    } else {
                        if (cx - k >= 0)   scan_cell(cbase, yy * GDIM + cx - k, q.x, q.y, best);
                        if (cx + k < GDIM) scan_cell(cbase, yy * GDIM + cx + k, q.x, q.y, best);
                    }
                }
            }
        }
    }

    // ---- Block partial (each query counted once: sub 0 contributes) ----
    __shared__ float sm[NTHR];
    __shared__ unsigned lastf;
    sm[t] = (sub == 0) ? best : 0.0f;
    __syncthreads();
    for (int off = NTHR / 2; off > 0; off >>= 1) {
        if (t < off) sm[t] += sm[t + off];
        __syncthreads();
    }
    if (t == 0) {
        g_part[bid] = sm[0];
        __threadfence();
        lastf = (atomicAdd(&g_done, 1u) == NSB - 1) ? 1u : 0u;
    }
    __syncthreads();

    if (lastf) {
        __threadfence();
        float a = 0.0f;
        #pragma unroll
        for (int k = 0; k < NSB / NTHR; k++)
            a += ((volatile float*)g_part)[t + k * NTHR];
        sm[t] = a;
        __syncthreads();
        for (int off = NTHR / 2; off > 0; off >>= 1) {
            if (t < off) sm[t] += sm[t + off];
            __syncthreads();
        }
        if (t == 0) {
            out[0] = sm[0] * (1.0f / (float)(BATCH * NPTS));
            g_done = 0;                           // reset for next replay
        }
        // Re-zero counts for the next replay (dead by now: all searches done)
        int4* cc = (int4*)g_ccnt;
        #pragma unroll 4
        for (int j = t; j < NTAB * NCELL / 4; j += NTHR)
            cc[j] = make_int4(0, 0, 0, 0);
    }
}

extern "C" void kernel_launch(void* const* d_in, const int* in_sizes, int n_in,
                              void* d_out, int out_size) {
    const float2* pred = (const float2*)d_in[0];
    const float2* gt   = (const float2*)d_in[1];

    k_fill<<<NQ / NTHR, NTHR>>>(pred, gt);
    k_search<<<NSB, NTHR>>>(pred, gt, (float*)d_out);
}